// round 1
// baseline (speedup 1.0000x reference)
#include <cuda_runtime.h>
#include <math.h>

#define BB 16
#define CC 768
#define HWN 4096
#define DD 256
#define MM 32
#define SCALE 20.0f            // 1/EPS
#define NORMC (-8.32554830f)   // -log(32+4096)

#define VT_ELEMS (BB*MM*DD)    // 131072

// ---- scratch (device globals; no allocations allowed) ----
__device__ float g_Z[BB*MM*HWN];     // 8 MB: Z[b,m,n] = scores^T / EPS
__device__ float g_inv[BB*HWN];      // per-row inverse L2 norm of x_proj
__device__ float g_u[BB*MM];
__device__ float g_v[BB*HWN];
__device__ float g_wn[MM*DD];        // normalized cluster weights

// ------------------------------------------------------------------
__global__ __launch_bounds__(256) void k_init(float* __restrict__ vt) {
    int i = blockIdx.x * 256 + threadIdx.x;
    if (i < BB*HWN) g_v[i] = 0.0f;
    if (i < VT_ELEMS) vt[i] = 0.0f;
}

// ------------------------------------------------------------------
__global__ __launch_bounds__(256) void k_wnorm(const float* __restrict__ v) {
    int r = blockIdx.x, t = threadIdx.x;
    float val = v[r*DD + t];
    float s = val * val;
    #pragma unroll
    for (int o = 16; o; o >>= 1) s += __shfl_xor_sync(~0u, s, o);
    __shared__ float red[8];
    if ((t & 31) == 0) red[t >> 5] = s;
    __syncthreads();
    if (t < 8) {
        float r2 = red[t];
        #pragma unroll
        for (int o = 4; o; o >>= 1) r2 += __shfl_xor_sync(0xff, r2, o, 8);
        if (t == 0) red[0] = r2;
    }
    __syncthreads();
    float inv = 1.0f / fmaxf(sqrtf(red[0]), 1e-12f);
    g_wn[r*DD + t] = val * inv;
}

// ------------------------------------------------------------------
// k1: fused 1x1-conv GEMM + bias + x_proj store + row-norm + scores (Z).
// Block tile: 64 spatial (n) x 256 channels (d), K=768 in chunks of 16.
// Thread layout: tx = t&15 (d groups), ty = t>>4 (n groups).
// Thread owns n = ty*4..+3, d = {4*tx..+3} + 64*j for j=0..3  (4x16 fp32 accs)
__global__ __launch_bounds__(256) void k1(const float* __restrict__ x,
                                          const float* __restrict__ W,
                                          const float* __restrict__ bias,
                                          float* __restrict__ xp) {
    const int b  = blockIdx.y;
    const int n0 = blockIdx.x * 64;
    const int t  = threadIdx.x;
    const int tx = t & 15, ty = t >> 4;

    __shared__ float sh[10304];        // 41.2 KB, aliased across phases
    float* As = sh;                    // 16 x 68
    float* Ws = sh + 1088;             // 16 x 260   (Ws[k][d])

    float4 acc[4][4];
    #pragma unroll
    for (int n = 0; n < 4; ++n)
        #pragma unroll
        for (int j = 0; j < 4; ++j) acc[n][j] = make_float4(0.f,0.f,0.f,0.f);

    const float* xb = x + (size_t)b * (CC*HWN);

    for (int kc = 0; kc < CC; kc += 16) {
        // A chunk: 16k x 64n, coalesced along n
        *(float4*)(As + ty*68 + tx*4) =
            *(const float4*)(xb + (size_t)(kc + ty)*HWN + n0 + tx*4);
        // W chunk: Ws[c][d], c = tx, d = ty + 16*i (coalesced along c in gmem)
        #pragma unroll
        for (int i = 0; i < 16; ++i)
            Ws[tx*260 + ty + 16*i] = W[(size_t)(ty + 16*i)*CC + kc + tx];
        __syncthreads();

        #pragma unroll
        for (int kk = 0; kk < 16; ++kk) {
            float4 a = *(float4*)(As + kk*68 + ty*4);
            float4 w[4];
            #pragma unroll
            for (int j = 0; j < 4; ++j)
                w[j] = *(float4*)(Ws + kk*260 + tx*4 + 64*j);
            #pragma unroll
            for (int j = 0; j < 4; ++j) {
                acc[0][j].x += a.x*w[j].x; acc[0][j].y += a.x*w[j].y;
                acc[0][j].z += a.x*w[j].z; acc[0][j].w += a.x*w[j].w;
                acc[1][j].x += a.y*w[j].x; acc[1][j].y += a.y*w[j].y;
                acc[1][j].z += a.y*w[j].z; acc[1][j].w += a.y*w[j].w;
                acc[2][j].x += a.z*w[j].x; acc[2][j].y += a.z*w[j].y;
                acc[2][j].z += a.z*w[j].z; acc[2][j].w += a.z*w[j].w;
                acc[3][j].x += a.w*w[j].x; acc[3][j].y += a.w*w[j].y;
                acc[3][j].z += a.w*w[j].z; acc[3][j].w += a.w*w[j].w;
            }
        }
        __syncthreads();
    }

    // bias
    #pragma unroll
    for (int j = 0; j < 4; ++j) {
        float4 bj = *(const float4*)(bias + tx*4 + 64*j);
        #pragma unroll
        for (int n = 0; n < 4; ++n) {
            acc[n][j].x += bj.x; acc[n][j].y += bj.y;
            acc[n][j].z += bj.z; acc[n][j].w += bj.w;
        }
    }

    // write x_proj, compute row norms
    float inv[4];
    #pragma unroll
    for (int n = 0; n < 4; ++n) {
        int row = b*HWN + n0 + ty*4 + n;
        float s = 0.f;
        #pragma unroll
        for (int j = 0; j < 4; ++j) {
            *(float4*)(xp + (size_t)row*DD + tx*4 + 64*j) = acc[n][j];
            s += acc[n][j].x*acc[n][j].x + acc[n][j].y*acc[n][j].y
               + acc[n][j].z*acc[n][j].z + acc[n][j].w*acc[n][j].w;
        }
        #pragma unroll
        for (int o = 8; o; o >>= 1) s += __shfl_xor_sync(~0u, s, o, 16);
        inv[n] = 1.0f / fmaxf(sqrtf(s), 1e-12f);
        if (tx == 0) g_inv[row] = inv[n];
    }

    // scores phase: reuse shared memory
    __syncthreads();
    float* Wn = sh;          // 32 x 256
    float* St = sh + 8192;   // 64 x 33
    for (int i = t; i < MM*DD; i += 256) Wn[i] = g_wn[i];
    __syncthreads();

    for (int m = 0; m < MM; ++m) {
        float part[4] = {0.f, 0.f, 0.f, 0.f};
        #pragma unroll
        for (int j = 0; j < 4; ++j) {
            float4 wv = *(float4*)(Wn + m*DD + tx*4 + 64*j);
            #pragma unroll
            for (int n = 0; n < 4; ++n)
                part[n] += acc[n][j].x*wv.x + acc[n][j].y*wv.y
                         + acc[n][j].z*wv.z + acc[n][j].w*wv.w;
        }
        #pragma unroll
        for (int n = 0; n < 4; ++n) {
            #pragma unroll
            for (int o = 8; o; o >>= 1)
                part[n] += __shfl_xor_sync(~0u, part[n], o, 16);
            if (tx == 0) St[(ty*4 + n)*33 + m] = part[n] * inv[n] * SCALE;
        }
    }
    __syncthreads();
    // store Z coalesced along n
    for (int i = t; i < 64*MM; i += 256) {
        int m = i >> 6, nn = i & 63;
        g_Z[(size_t)(b*MM + m)*HWN + n0 + nn] = St[nn*33 + m];
    }
}

// ------------------------------------------------------------------
// u[b,m] = norm - lse_n(Z[b,m,:] + v[b,:]) ; one block per (b,m)
__global__ __launch_bounds__(256) void k2a() {
    int bm = blockIdx.x;
    int b  = bm >> 5;
    const float* z  = g_Z + (size_t)bm * HWN;
    const float* vv = g_v + b * HWN;
    int t = threadIdx.x;

    float vals[16];
    float mx = -1e30f;
    #pragma unroll
    for (int i = 0; i < 16; ++i) {
        int idx = t + i*256;
        vals[i] = z[idx] + vv[idx];
        mx = fmaxf(mx, vals[i]);
    }
    __shared__ float red[8];
    #pragma unroll
    for (int o = 16; o; o >>= 1) mx = fmaxf(mx, __shfl_xor_sync(~0u, mx, o));
    if ((t & 31) == 0) red[t >> 5] = mx;
    __syncthreads();
    if (t < 8) {
        float r = red[t];
        #pragma unroll
        for (int o = 4; o; o >>= 1) r = fmaxf(r, __shfl_xor_sync(0xff, r, o, 8));
        if (t == 0) red[0] = r;
    }
    __syncthreads();
    mx = red[0];
    __syncthreads();

    float s = 0.f;
    #pragma unroll
    for (int i = 0; i < 16; ++i) s += expf(vals[i] - mx);
    #pragma unroll
    for (int o = 16; o; o >>= 1) s += __shfl_xor_sync(~0u, s, o);
    if ((t & 31) == 0) red[t >> 5] = s;
    __syncthreads();
    if (t == 0) {
        float tot = 0.f;
        #pragma unroll
        for (int i = 0; i < 8; ++i) tot += red[i];
        g_u[bm] = NORMC - (mx + logf(tot));
    }
}

// v[b,n] = norm - lse_m(Z[b,:,n] + u[b,:]) ; one thread per (b,n)
__global__ __launch_bounds__(256) void k2b() {
    int gid = blockIdx.x*256 + threadIdx.x;
    int b = gid >> 12;
    int n = gid & (HWN - 1);
    __shared__ float us[MM];
    if (threadIdx.x < MM) us[threadIdx.x] = g_u[b*MM + threadIdx.x];
    __syncthreads();
    float vals[MM];
    float mx = -1e30f;
    #pragma unroll
    for (int m = 0; m < MM; ++m) {
        vals[m] = g_Z[(size_t)(b*MM + m)*HWN + n] + us[m];
        mx = fmaxf(mx, vals[m]);
    }
    float s = 0.f;
    #pragma unroll
    for (int m = 0; m < MM; ++m) s += expf(vals[m] - mx);
    g_v[gid] = NORMC - (mx + logf(s));
}

// ------------------------------------------------------------------
// v_tilde[b,m,d] += sum_n xf[b,n,d] * exp(Z[m,n]+u[m]+v[n]-norm)
// Block: (b, 256-n chunk); thread t owns d = t, 32 m-accumulators.
__global__ __launch_bounds__(256) void k3(const float* __restrict__ xp,
                                          float* __restrict__ vt) {
    int b  = blockIdx.y;
    int n0 = blockIdx.x * 256;
    int t  = threadIdx.x;
    __shared__ float sw[64*36];
    __shared__ float us[MM];
    if (t < MM) us[t] = g_u[b*MM + t];
    float acc[MM];
    #pragma unroll
    for (int m = 0; m < MM; ++m) acc[m] = 0.f;
    __syncthreads();

    for (int sub = 0; sub < 4; ++sub) {
        int ns = n0 + sub*64;
        __syncthreads();
        #pragma unroll
        for (int p = 0; p < 8; ++p) {
            int idx = t + p*256;
            int m = idx >> 6, nn = idx & 63;
            float zv = g_Z[(size_t)(b*MM + m)*HWN + ns + nn];
            sw[nn*36 + m] = expf(zv + us[m] + g_v[b*HWN + ns + nn] - NORMC);
        }
        __syncthreads();
        #pragma unroll 4
        for (int nn = 0; nn < 64; ++nn) {
            float xv = xp[(size_t)(b*HWN + ns + nn)*DD + t]
                     * g_inv[b*HWN + ns + nn];
            #pragma unroll
            for (int m4 = 0; m4 < 8; ++m4) {
                float4 w4 = *(float4*)(sw + nn*36 + m4*4);
                acc[m4*4+0] += xv * w4.x;
                acc[m4*4+1] += xv * w4.y;
                acc[m4*4+2] += xv * w4.z;
                acc[m4*4+3] += xv * w4.w;
            }
        }
    }
    #pragma unroll
    for (int m = 0; m < MM; ++m)
        atomicAdd(&vt[(size_t)(b*MM + m)*DD + t], acc[m]);
}

// ------------------------------------------------------------------
extern "C" void kernel_launch(void* const* d_in, const int* in_sizes, int n_in,
                              void* d_out, int out_size) {
    (void)in_sizes; (void)n_in; (void)out_size;
    const float* x    = (const float*)d_in[0];   // [16,768,64,64]
    const float* W    = (const float*)d_in[1];   // [256,768]
    const float* bias = (const float*)d_in[2];   // [256]
    const float* v    = (const float*)d_in[3];   // [32,256]

    float* out = (float*)d_out;
    float* vt  = out;                 // v_tilde [16,32,256]
    float* xp  = out + VT_ELEMS;      // x_proj  [16,4096,256]

    k_init<<<512, 256>>>(vt);
    k_wnorm<<<32, 256>>>(v);
    k1<<<dim3(64, 16), 256>>>(x, W, bias, xp);
    for (int it = 0; it < 3; ++it) {
        k2a<<<512, 256>>>();
        k2b<<<256, 256>>>();
    }
    k3<<<dim3(16, 16), 256>>>(xp, vt);
}

// round 4
// speedup vs baseline: 1.6849x; 1.6849x over previous
#include <cuda_runtime.h>
#include <cuda_bf16.h>
#include <cstdint>
#include <math.h>

#define BB 16
#define CC 768
#define HWN 4096
#define DD 256
#define MM 32
#define SCALE 20.0f            // 1/EPS
#define NORMC (-8.32554830f)   // -log(32+4096)
#define VT_ELEMS (BB*MM*DD)

// ---- scratch (device globals; no allocations allowed) ----
__device__ float g_Z[BB*MM*HWN];     // 8 MB: Z[b,m,n]
__device__ float g_inv[BB*HWN];
__device__ float g_u[BB*MM];
__device__ float g_v[BB*HWN];
__device__ float g_wn[MM*DD];
// W pre-split into per-lane mma A-fragments: [term 2][dtile 16][ktile 48][lane 32][4 words]
__device__ __align__(16) unsigned g_wf[2*98304];

__device__ __forceinline__ uint32_t smem_u32(const void* p) {
    uint32_t a;
    asm("{ .reg .u64 t; cvta.to.shared.u64 t, %1; cvt.u32.u64 %0, t; }" : "=r"(a) : "l"(p));
    return a;
}

__device__ __forceinline__ void split2(float a, float b, unsigned &hi, unsigned &lo) {
    __nv_bfloat16 ha = __float2bfloat16_rn(a), hb = __float2bfloat16_rn(b);
    float ra = a - __bfloat162float(ha), rb = b - __bfloat162float(hb);
    __nv_bfloat16 la = __float2bfloat16_rn(ra), lb = __float2bfloat16_rn(rb);
    hi = (unsigned)__bfloat16_as_ushort(ha) | ((unsigned)__bfloat16_as_ushort(hb) << 16);
    lo = (unsigned)__bfloat16_as_ushort(la) | ((unsigned)__bfloat16_as_ushort(lb) << 16);
}

#define LDSM_T(r0,r1,r2,r3,addr) \
    asm volatile("ldmatrix.sync.aligned.m8n8.x4.trans.shared.b16 {%0,%1,%2,%3}, [%4];" \
        : "=r"(r0), "=r"(r1), "=r"(r2), "=r"(r3) : "r"(addr))

#define MMA_BF16(acc, a, b0v, b1v) \
    asm volatile("mma.sync.aligned.m16n8k16.row.col.f32.bf16.bf16.f32 " \
        "{%0,%1,%2,%3}, {%4,%5,%6,%7}, {%8,%9}, {%0,%1,%2,%3};" \
        : "+f"((acc)[0]), "+f"((acc)[1]), "+f"((acc)[2]), "+f"((acc)[3]) \
        : "r"((a).x), "r"((a).y), "r"((a).z), "r"((a).w), "r"(b0v), "r"(b1v))

// ------------------------------------------------------------------
__global__ __launch_bounds__(256) void k_init(float* __restrict__ vt) {
    int i = blockIdx.x * 256 + threadIdx.x;
    if (i < BB*HWN) g_v[i] = 0.0f;
    if (i < VT_ELEMS) vt[i] = 0.0f;
}

// ------------------------------------------------------------------
__global__ __launch_bounds__(256) void k_wnorm(const float* __restrict__ v) {
    int r = blockIdx.x, t = threadIdx.x;
    float val = v[r*DD + t];
    float s = val * val;
    #pragma unroll
    for (int o = 16; o; o >>= 1) s += __shfl_xor_sync(~0u, s, o);
    __shared__ float red[8];
    if ((t & 31) == 0) red[t >> 5] = s;
    __syncthreads();
    if (t < 8) {
        float r2 = red[t];
        #pragma unroll
        for (int o = 4; o; o >>= 1) r2 += __shfl_xor_sync(0xff, r2, o, 8);
        if (t == 0) red[0] = r2;
    }
    __syncthreads();
    float inv = 1.0f / fmaxf(sqrtf(red[0]), 1e-12f);
    g_wn[r*DD + t] = val * inv;
}

// ------------------------------------------------------------------
// Pre-split W (fp32 -> bf16 hi/lo) into per-lane A-fragment layout.
//   d = dt*16 + (lane>>2) + (w&1)*8 ; c = kt*16 + (lane&3)*2 + (w>>1)*8
__global__ __launch_bounds__(256) void k_wsplit(const float* __restrict__ W) {
    int gid = blockIdx.x*256 + threadIdx.x;      // 0..98303
    int w = gid & 3, lane = (gid >> 2) & 31, tile = gid >> 7;
    int kt = tile % 48, dt = tile / 48;
    int d = dt*16 + (lane >> 2) + (w & 1)*8;
    int c = kt*16 + (lane & 3)*2 + (w >> 1)*8;
    unsigned hi, lo;
    split2(W[(size_t)d*CC + c], W[(size_t)d*CC + c + 1], hi, lo);
    g_wf[gid] = hi;
    g_wf[98304 + gid] = lo;
}

// ------------------------------------------------------------------
// k1_mma: x_proj[b,n,d] = W x + bias via mma.sync bf16 3-term split.
// CTA: 256 d x 128 n, 512 threads (16 warps). Warp: 32 d x 64 n.
#define XPITCH 304                      // smem row pitch (bytes) for x tiles
#define XLO    9728                     // offset of lo-term tile (32*304)
#define EPITCH 260                      // epilogue float pitch
#define SMEM_SZ 66560                   // 64 * 260 * 4

__global__ __launch_bounds__(512) void k1_mma(const float* __restrict__ x,
                                              const float* __restrict__ bias,
                                              float* __restrict__ xp) {
    extern __shared__ char smc[];
    const uint32_t sb = smem_u32(smc);
    const int b = blockIdx.y, n0 = blockIdx.x * 128;
    const int t = threadIdx.x, w = t >> 5, lane = t & 31;
    const int nw = (w >> 3) * 64;

    float acc[2][8][4];
    #pragma unroll
    for (int mt = 0; mt < 2; ++mt)
        #pragma unroll
        for (int nt = 0; nt < 8; ++nt)
            #pragma unroll
            for (int i = 0; i < 4; ++i) acc[mt][nt][i] = 0.f;

    const float* xb = x + (size_t)b * CC * HWN + n0;

    for (int kc = 0; kc < CC; kc += 32) {
        // stage x chunk: [32 c][128 n] fp32 -> bf16 hi/lo in smem
        // 32 rows x 32 float4 = 1024 items over 512 threads -> 2 iters
        #pragma unroll
        for (int i = 0; i < 2; ++i) {
            int idx = t + i*512;
            int c = idx >> 5, n4 = idx & 31;
            float4 v = *(const float4*)(xb + (size_t)(kc + c)*HWN + n4*4);
            unsigned h01, l01, h23, l23;
            split2(v.x, v.y, h01, l01);
            split2(v.z, v.w, h23, l23);
            char* row = smc + c*XPITCH + n4*8;
            *(uint2*)row         = make_uint2(h01, h23);
            *(uint2*)(row + XLO) = make_uint2(l01, l23);
        }
        __syncthreads();

        #pragma unroll
        for (int ks = 0; ks < 32; ks += 16) {
            const int kt = (kc + ks) >> 4;
            uint4 ah[2], al[2];
            #pragma unroll
            for (int mt = 0; mt < 2; ++mt) {
                int dt = (w & 7)*2 + mt;
                int off = ((dt*48 + kt)*32 + lane)*4;
                ah[mt] = *(const uint4*)(g_wf + off);
                al[mt] = *(const uint4*)(g_wf + 98304 + off);
            }
            #pragma unroll
            for (int j = 0; j < 4; ++j) {
                uint32_t baddr = sb + (uint32_t)((ks + (lane & 15))*XPITCH
                               + (nw + j*16 + ((lane >> 4) << 3))*2);
                unsigned bh0,bh1,bh2,bh3, bl0,bl1,bl2,bl3;
                LDSM_T(bh0,bh1,bh2,bh3, baddr);
                LDSM_T(bl0,bl1,bl2,bl3, baddr + XLO);
                #pragma unroll
                for (int mt = 0; mt < 2; ++mt) {
                    MMA_BF16(acc[mt][2*j],   ah[mt], bh0, bh1);
                    MMA_BF16(acc[mt][2*j],   ah[mt], bl0, bl1);
                    MMA_BF16(acc[mt][2*j],   al[mt], bh0, bh1);
                    MMA_BF16(acc[mt][2*j+1], ah[mt], bh2, bh3);
                    MMA_BF16(acc[mt][2*j+1], ah[mt], bl2, bl3);
                    MMA_BF16(acc[mt][2*j+1], al[mt], bh2, bh3);
                }
            }
        }
        __syncthreads();
    }

    // epilogue: stage through smem per 64-n half for coalesced stores
    float* s_ep = (float*)smc;
    const float4* bias4 = (const float4*)bias;
    #pragma unroll
    for (int p = 0; p < 2; ++p) {
        __syncthreads();
        if ((w >> 3) == p) {
            #pragma unroll
            for (int mt = 0; mt < 2; ++mt) {
                int d = (w & 7)*32 + mt*16 + (lane >> 2);
                #pragma unroll
                for (int nt = 0; nt < 8; ++nt) {
                    int nl = nt*8 + (lane & 3)*2;
                    s_ep[nl*EPITCH + d]           = acc[mt][nt][0];
                    s_ep[(nl+1)*EPITCH + d]       = acc[mt][nt][1];
                    s_ep[nl*EPITCH + d + 8]       = acc[mt][nt][2];
                    s_ep[(nl+1)*EPITCH + d + 8]   = acc[mt][nt][3];
                }
            }
        }
        __syncthreads();
        #pragma unroll
        for (int i = 0; i < 8; ++i) {
            int idx = t + i*512;
            int row = idx >> 6, c4 = idx & 63;
            float4 v = *(float4*)(s_ep + row*EPITCH + c4*4);
            float4 bv = bias4[c4];
            v.x += bv.x; v.y += bv.y; v.z += bv.z; v.w += bv.w;
            *(float4*)(xp + (size_t)(b*HWN + n0 + p*64 + row)*DD + c4*4) = v;
        }
    }
}

// ------------------------------------------------------------------
// k1b: row L2 norms + cluster scores -> Z (reads x_proj)
__global__ __launch_bounds__(256) void k1b(const float* __restrict__ xp) {
    const int b = blockIdx.y, n0 = blockIdx.x * 64;
    const int t = threadIdx.x, tx = t & 15, ty = t >> 4;
    __shared__ float sh[8192 + 64*33];

    float4 acc[4][4];
    #pragma unroll
    for (int n = 0; n < 4; ++n) {
        int row = b*HWN + n0 + ty*4 + n;
        #pragma unroll
        for (int j = 0; j < 4; ++j)
            acc[n][j] = *(const float4*)(xp + (size_t)row*DD + tx*4 + 64*j);
    }

    float inv[4];
    #pragma unroll
    for (int n = 0; n < 4; ++n) {
        int row = b*HWN + n0 + ty*4 + n;
        float s = 0.f;
        #pragma unroll
        for (int j = 0; j < 4; ++j)
            s += acc[n][j].x*acc[n][j].x + acc[n][j].y*acc[n][j].y
               + acc[n][j].z*acc[n][j].z + acc[n][j].w*acc[n][j].w;
        #pragma unroll
        for (int o = 8; o; o >>= 1) s += __shfl_xor_sync(~0u, s, o, 16);
        inv[n] = 1.0f / fmaxf(sqrtf(s), 1e-12f);
        if (tx == 0) g_inv[row] = inv[n];
    }

    float* Wn = sh;
    float* St = sh + 8192;
    for (int i = t; i < MM*DD; i += 256) Wn[i] = g_wn[i];
    __syncthreads();

    for (int m = 0; m < MM; ++m) {
        float part[4] = {0.f, 0.f, 0.f, 0.f};
        #pragma unroll
        for (int j = 0; j < 4; ++j) {
            float4 wv = *(float4*)(Wn + m*DD + tx*4 + 64*j);
            #pragma unroll
            for (int n = 0; n < 4; ++n)
                part[n] += acc[n][j].x*wv.x + acc[n][j].y*wv.y
                         + acc[n][j].z*wv.z + acc[n][j].w*wv.w;
        }
        #pragma unroll
        for (int n = 0; n < 4; ++n) {
            #pragma unroll
            for (int o = 8; o; o >>= 1)
                part[n] += __shfl_xor_sync(~0u, part[n], o, 16);
            if (tx == 0) St[(ty*4 + n)*33 + m] = part[n] * inv[n] * SCALE;
        }
    }
    __syncthreads();
    for (int i = t; i < 64*MM; i += 256) {
        int m = i >> 6, nn = i & 63;
        g_Z[(size_t)(b*MM + m)*HWN + n0 + nn] = St[nn*33 + m];
    }
}

// ------------------------------------------------------------------
__global__ __launch_bounds__(256) void k2a() {
    int bm = blockIdx.x;
    int b  = bm >> 5;
    const float* z  = g_Z + (size_t)bm * HWN;
    const float* vv = g_v + b * HWN;
    int t = threadIdx.x;

    float vals[16];
    float mx = -1e30f;
    #pragma unroll
    for (int i = 0; i < 16; ++i) {
        int idx = t + i*256;
        vals[i] = z[idx] + vv[idx];
        mx = fmaxf(mx, vals[i]);
    }
    __shared__ float red[8];
    #pragma unroll
    for (int o = 16; o; o >>= 1) mx = fmaxf(mx, __shfl_xor_sync(~0u, mx, o));
    if ((t & 31) == 0) red[t >> 5] = mx;
    __syncthreads();
    if (t < 8) {
        float r = red[t];
        #pragma unroll
        for (int o = 4; o; o >>= 1) r = fmaxf(r, __shfl_xor_sync(0xff, r, o, 8));
        if (t == 0) red[0] = r;
    }
    __syncthreads();
    mx = red[0];
    __syncthreads();

    float s = 0.f;
    #pragma unroll
    for (int i = 0; i < 16; ++i) s += expf(vals[i] - mx);
    #pragma unroll
    for (int o = 16; o; o >>= 1) s += __shfl_xor_sync(~0u, s, o);
    if ((t & 31) == 0) red[t >> 5] = s;
    __syncthreads();
    if (t == 0) {
        float tot = 0.f;
        #pragma unroll
        for (int i = 0; i < 8; ++i) tot += red[i];
        g_u[bm] = NORMC - (mx + logf(tot));
    }
}

__global__ __launch_bounds__(256) void k2b() {
    int gid = blockIdx.x*256 + threadIdx.x;
    int b = gid >> 12;
    int n = gid & (HWN - 1);
    __shared__ float us[MM];
    if (threadIdx.x < MM) us[threadIdx.x] = g_u[b*MM + threadIdx.x];
    __syncthreads();
    float vals[MM];
    float mx = -1e30f;
    #pragma unroll
    for (int m = 0; m < MM; ++m) {
        vals[m] = g_Z[(size_t)(b*MM + m)*HWN + n] + us[m];
        mx = fmaxf(mx, vals[m]);
    }
    float s = 0.f;
    #pragma unroll
    for (int m = 0; m < MM; ++m) s += expf(vals[m] - mx);
    g_v[gid] = NORMC - (mx + logf(s));
}

// ------------------------------------------------------------------
__global__ __launch_bounds__(256) void k3(const float* __restrict__ xp,
                                          float* __restrict__ vt) {
    int b  = blockIdx.y;
    int n0 = blockIdx.x * 256;
    int t  = threadIdx.x;
    __shared__ float sw[64*36];
    __shared__ float us[MM];
    if (t < MM) us[t] = g_u[b*MM + t];
    float acc[MM];
    #pragma unroll
    for (int m = 0; m < MM; ++m) acc[m] = 0.f;
    __syncthreads();

    for (int sub = 0; sub < 4; ++sub) {
        int ns = n0 + sub*64;
        __syncthreads();
        #pragma unroll
        for (int p = 0; p < 8; ++p) {
            int idx = t + p*256;
            int m = idx >> 6, nn = idx & 63;
            float zv = g_Z[(size_t)(b*MM + m)*HWN + ns + nn];
            sw[nn*36 + m] = expf(zv + us[m] + g_v[b*HWN + ns + nn] - NORMC);
        }
        __syncthreads();
        #pragma unroll 4
        for (int nn = 0; nn < 64; ++nn) {
            float xv = xp[(size_t)(b*HWN + ns + nn)*DD + t]
                     * g_inv[b*HWN + ns + nn];
            #pragma unroll
            for (int m4 = 0; m4 < 8; ++m4) {
                float4 w4 = *(float4*)(sw + nn*36 + m4*4);
                acc[m4*4+0] += xv * w4.x;
                acc[m4*4+1] += xv * w4.y;
                acc[m4*4+2] += xv * w4.z;
                acc[m4*4+3] += xv * w4.w;
            }
        }
    }
    #pragma unroll
    for (int m = 0; m < MM; ++m)
        atomicAdd(&vt[(size_t)(b*MM + m)*DD + t], acc[m]);
}

// ------------------------------------------------------------------
extern "C" void kernel_launch(void* const* d_in, const int* in_sizes, int n_in,
                              void* d_out, int out_size) {
    (void)in_sizes; (void)n_in; (void)out_size;
    const float* x    = (const float*)d_in[0];   // [16,768,64,64]
    const float* W    = (const float*)d_in[1];   // [256,768]
    const float* bias = (const float*)d_in[2];   // [256]
    const float* v    = (const float*)d_in[3];   // [32,256]

    float* out = (float*)d_out;
    float* vt  = out;                 // v_tilde [16,32,256]
    float* xp  = out + VT_ELEMS;      // x_proj  [16,4096,256]

    cudaFuncSetAttribute(k1_mma, cudaFuncAttributeMaxDynamicSharedMemorySize, SMEM_SZ);

    k_init<<<512, 256>>>(vt);
    k_wnorm<<<32, 256>>>(v);
    k_wsplit<<<384, 256>>>(W);
    k1_mma<<<dim3(32, 16), 512, SMEM_SZ>>>(x, bias, xp);
    k1b<<<dim3(64, 16), 256>>>(xp);
    for (int it = 0; it < 3; ++it) {
        k2a<<<512, 256>>>();
        k2b<<<256, 256>>>();
    }
    k3<<<dim3(16, 16), 256>>>(xp, vt);
}

// round 5
// speedup vs baseline: 1.8550x; 1.1010x over previous
#include <cuda_runtime.h>
#include <cuda_bf16.h>
#include <cstdint>
#include <math.h>

#define BB 16
#define CC 768
#define HWN 4096
#define DD 256
#define MM 32
#define SCALE 20.0f            // 1/EPS
#define NORMC (-8.32554830f)   // -log(32+4096)
#define VT_ELEMS (BB*MM*DD)

// ---- scratch (device globals; no allocations allowed) ----
__device__ float g_Z[BB*MM*HWN];     // 8 MB: Z[b,m,n]
__device__ float g_inv[BB*HWN];
__device__ float g_u[BB*MM];
__device__ float g_v[BB*HWN];
__device__ float g_wn[MM*DD];
// W pre-split into per-lane mma A-fragments: [term 2][dtile 16][ktile 48][lane 32][4 words]
__device__ __align__(16) unsigned g_wf[2*98304];

__device__ __forceinline__ uint32_t smem_u32(const void* p) {
    uint32_t a;
    asm("{ .reg .u64 t; cvta.to.shared.u64 t, %1; cvt.u32.u64 %0, t; }" : "=r"(a) : "l"(p));
    return a;
}

__device__ __forceinline__ void split2(float a, float b, unsigned &hi, unsigned &lo) {
    __nv_bfloat16 ha = __float2bfloat16_rn(a), hb = __float2bfloat16_rn(b);
    float ra = a - __bfloat162float(ha), rb = b - __bfloat162float(hb);
    __nv_bfloat16 la = __float2bfloat16_rn(ra), lb = __float2bfloat16_rn(rb);
    hi = (unsigned)__bfloat16_as_ushort(ha) | ((unsigned)__bfloat16_as_ushort(hb) << 16);
    lo = (unsigned)__bfloat16_as_ushort(la) | ((unsigned)__bfloat16_as_ushort(lb) << 16);
}

#define LDSM_T(r0,r1,r2,r3,addr) \
    asm volatile("ldmatrix.sync.aligned.m8n8.x4.trans.shared.b16 {%0,%1,%2,%3}, [%4];" \
        : "=r"(r0), "=r"(r1), "=r"(r2), "=r"(r3) : "r"(addr))

#define MMA_BF16(acc, a, b0v, b1v) \
    asm volatile("mma.sync.aligned.m16n8k16.row.col.f32.bf16.bf16.f32 " \
        "{%0,%1,%2,%3}, {%4,%5,%6,%7}, {%8,%9}, {%0,%1,%2,%3};" \
        : "+f"((acc)[0]), "+f"((acc)[1]), "+f"((acc)[2]), "+f"((acc)[3]) \
        : "r"((a).x), "r"((a).y), "r"((a).z), "r"((a).w), "r"(b0v), "r"(b1v))

// ------------------------------------------------------------------
__global__ __launch_bounds__(256) void k_init(float* __restrict__ vt) {
    int i = blockIdx.x * 256 + threadIdx.x;
    if (i < BB*HWN) g_v[i] = 0.0f;
    if (i < VT_ELEMS) vt[i] = 0.0f;
}

// ------------------------------------------------------------------
__global__ __launch_bounds__(256) void k_wnorm(const float* __restrict__ v) {
    int r = blockIdx.x, t = threadIdx.x;
    float val = v[r*DD + t];
    float s = val * val;
    #pragma unroll
    for (int o = 16; o; o >>= 1) s += __shfl_xor_sync(~0u, s, o);
    __shared__ float red[8];
    if ((t & 31) == 0) red[t >> 5] = s;
    __syncthreads();
    if (t < 8) {
        float r2 = red[t];
        #pragma unroll
        for (int o = 4; o; o >>= 1) r2 += __shfl_xor_sync(0xff, r2, o, 8);
        if (t == 0) red[0] = r2;
    }
    __syncthreads();
    float inv = 1.0f / fmaxf(sqrtf(red[0]), 1e-12f);
    g_wn[r*DD + t] = val * inv;
}

// ------------------------------------------------------------------
// Pre-split W (fp32 -> bf16 hi/lo) into per-lane A-fragment layout.
//   d = dt*16 + (lane>>2) + (w&1)*8 ; c = kt*16 + (lane&3)*2 + (w>>1)*8
__global__ __launch_bounds__(256) void k_wsplit(const float* __restrict__ W) {
    int gid = blockIdx.x*256 + threadIdx.x;      // 0..98303
    int w = gid & 3, lane = (gid >> 2) & 31, tile = gid >> 7;
    int kt = tile % 48, dt = tile / 48;
    int d = dt*16 + (lane >> 2) + (w & 1)*8;
    int c = kt*16 + (lane & 3)*2 + (w >> 1)*8;
    unsigned hi, lo;
    split2(W[(size_t)d*CC + c], W[(size_t)d*CC + c + 1], hi, lo);
    g_wf[gid] = hi;
    g_wf[98304 + gid] = lo;
}

// ------------------------------------------------------------------
// k1_mma: x_proj[b,n,d] = W x + bias via mma.sync bf16 3-term split.
// CTA: 256 d x 128 n, 512 threads (16 warps). Warp: 32 d x 64 n.
// Double-buffered x staging: STS(k) ; LDG(k+1) ; sync ; MMA(k).
#define XPITCH 304                      // smem row pitch (bytes) for x tiles
#define XLO    9728                     // hi->lo offset within one buffer
#define XBUF   19456                    // one x buffer (hi + lo)
#define EP_OFF 38912                    // epilogue staging region
#define EPITCH 260                      // epilogue float pitch
#define SMEM_SZ (EP_OFF + 66560)        // 105472

__global__ __launch_bounds__(512) void k1_mma(const float* __restrict__ x,
                                              const float* __restrict__ bias,
                                              float* __restrict__ xp) {
    extern __shared__ char smc[];
    const uint32_t sb = smem_u32(smc);
    const int b = blockIdx.y, n0 = blockIdx.x * 128;
    const int t = threadIdx.x, w = t >> 5, lane = t & 31;
    const int nw = (w >> 3) * 64;

    float acc[2][8][4];
    #pragma unroll
    for (int mt = 0; mt < 2; ++mt)
        #pragma unroll
        for (int nt = 0; nt < 8; ++nt)
            #pragma unroll
            for (int i = 0; i < 4; ++i) acc[mt][nt][i] = 0.f;

    const float* xb = x + (size_t)b * CC * HWN + n0;
    const int c0 = t >> 5;              // staging row for item 0 (0..15)
    const int c1 = c0 + 16;             // staging row for item 1 (16..31)
    const int n4 = t & 31;              // float4 column

    // prefetch chunk 0
    float4 v0 = *(const float4*)(xb + (size_t)c0*HWN + n4*4);
    float4 v1 = *(const float4*)(xb + (size_t)c1*HWN + n4*4);

    int buf = 0;
    for (int kc = 0; kc < CC; kc += 32, buf ^= 1) {
        // STS prefetched chunk into buf
        {
            char* base = smc + buf*XBUF;
            unsigned h01,l01,h23,l23;
            split2(v0.x, v0.y, h01, l01);
            split2(v0.z, v0.w, h23, l23);
            char* r0 = base + c0*XPITCH + n4*8;
            *(uint2*)r0         = make_uint2(h01, h23);
            *(uint2*)(r0 + XLO) = make_uint2(l01, l23);
            split2(v1.x, v1.y, h01, l01);
            split2(v1.z, v1.w, h23, l23);
            char* r1 = base + c1*XPITCH + n4*8;
            *(uint2*)r1         = make_uint2(h01, h23);
            *(uint2*)(r1 + XLO) = make_uint2(l01, l23);
        }
        // prefetch next chunk (overlaps MMA below)
        if (kc + 32 < CC) {
            v0 = *(const float4*)(xb + (size_t)(kc + 32 + c0)*HWN + n4*4);
            v1 = *(const float4*)(xb + (size_t)(kc + 32 + c1)*HWN + n4*4);
        }
        __syncthreads();

        const uint32_t sxb = sb + buf*XBUF;
        #pragma unroll
        for (int ks = 0; ks < 32; ks += 16) {
            const int kt = (kc + ks) >> 4;
            uint4 ah[2], al[2];
            #pragma unroll
            for (int mt = 0; mt < 2; ++mt) {
                int dt = (w & 7)*2 + mt;
                int off = ((dt*48 + kt)*32 + lane)*4;
                ah[mt] = *(const uint4*)(g_wf + off);
                al[mt] = *(const uint4*)(g_wf + 98304 + off);
            }
            #pragma unroll
            for (int j = 0; j < 4; ++j) {
                uint32_t baddr = sxb + (uint32_t)((ks + (lane & 15))*XPITCH
                               + (nw + j*16 + ((lane >> 4) << 3))*2);
                unsigned bh0,bh1,bh2,bh3, bl0,bl1,bl2,bl3;
                LDSM_T(bh0,bh1,bh2,bh3, baddr);
                LDSM_T(bl0,bl1,bl2,bl3, baddr + XLO);
                #pragma unroll
                for (int mt = 0; mt < 2; ++mt) {
                    MMA_BF16(acc[mt][2*j],   ah[mt], bh0, bh1);
                    MMA_BF16(acc[mt][2*j],   ah[mt], bl0, bl1);
                    MMA_BF16(acc[mt][2*j],   al[mt], bh0, bh1);
                    MMA_BF16(acc[mt][2*j+1], ah[mt], bh2, bh3);
                    MMA_BF16(acc[mt][2*j+1], ah[mt], bl2, bl3);
                    MMA_BF16(acc[mt][2*j+1], al[mt], bh2, bh3);
                }
            }
        }
        // no trailing sync needed: next iteration's STS targets the other
        // buffer, whose readers all finished before this iteration's sync.
    }

    // epilogue: stage through smem per 64-n half for coalesced stores
    float* s_ep = (float*)(smc + EP_OFF);
    const float4* bias4 = (const float4*)bias;
    #pragma unroll
    for (int p = 0; p < 2; ++p) {
        __syncthreads();
        if ((w >> 3) == p) {
            #pragma unroll
            for (int mt = 0; mt < 2; ++mt) {
                int d = (w & 7)*32 + mt*16 + (lane >> 2);
                #pragma unroll
                for (int nt = 0; nt < 8; ++nt) {
                    int nl = nt*8 + (lane & 3)*2;
                    s_ep[nl*EPITCH + d]           = acc[mt][nt][0];
                    s_ep[(nl+1)*EPITCH + d]       = acc[mt][nt][1];
                    s_ep[nl*EPITCH + d + 8]       = acc[mt][nt][2];
                    s_ep[(nl+1)*EPITCH + d + 8]   = acc[mt][nt][3];
                }
            }
        }
        __syncthreads();
        #pragma unroll
        for (int i = 0; i < 8; ++i) {
            int idx = t + i*512;
            int row = idx >> 6, c4 = idx & 63;
            float4 v = *(float4*)(s_ep + row*EPITCH + c4*4);
            float4 bv = bias4[c4];
            v.x += bv.x; v.y += bv.y; v.z += bv.z; v.w += bv.w;
            *(float4*)(xp + (size_t)(b*HWN + n0 + p*64 + row)*DD + c4*4) = v;
        }
    }
}

// ------------------------------------------------------------------
// k1b: row L2 norms + cluster scores -> Z (reads x_proj)
__global__ __launch_bounds__(256) void k1b(const float* __restrict__ xp) {
    const int b = blockIdx.y, n0 = blockIdx.x * 64;
    const int t = threadIdx.x, tx = t & 15, ty = t >> 4;
    __shared__ float sh[8192 + 64*33];

    float4 acc[4][4];
    #pragma unroll
    for (int n = 0; n < 4; ++n) {
        int row = b*HWN + n0 + ty*4 + n;
        #pragma unroll
        for (int j = 0; j < 4; ++j)
            acc[n][j] = *(const float4*)(xp + (size_t)row*DD + tx*4 + 64*j);
    }

    float inv[4];
    #pragma unroll
    for (int n = 0; n < 4; ++n) {
        int row = b*HWN + n0 + ty*4 + n;
        float s = 0.f;
        #pragma unroll
        for (int j = 0; j < 4; ++j)
            s += acc[n][j].x*acc[n][j].x + acc[n][j].y*acc[n][j].y
               + acc[n][j].z*acc[n][j].z + acc[n][j].w*acc[n][j].w;
        #pragma unroll
        for (int o = 8; o; o >>= 1) s += __shfl_xor_sync(~0u, s, o, 16);
        inv[n] = 1.0f / fmaxf(sqrtf(s), 1e-12f);
        if (tx == 0) g_inv[row] = inv[n];
    }

    float* Wn = sh;
    float* St = sh + 8192;
    for (int i = t; i < MM*DD; i += 256) Wn[i] = g_wn[i];
    __syncthreads();

    for (int m = 0; m < MM; ++m) {
        float part[4] = {0.f, 0.f, 0.f, 0.f};
        #pragma unroll
        for (int j = 0; j < 4; ++j) {
            float4 wv = *(float4*)(Wn + m*DD + tx*4 + 64*j);
            #pragma unroll
            for (int n = 0; n < 4; ++n)
                part[n] += acc[n][j].x*wv.x + acc[n][j].y*wv.y
                         + acc[n][j].z*wv.z + acc[n][j].w*wv.w;
        }
        #pragma unroll
        for (int n = 0; n < 4; ++n) {
            #pragma unroll
            for (int o = 8; o; o >>= 1)
                part[n] += __shfl_xor_sync(~0u, part[n], o, 16);
            if (tx == 0) St[(ty*4 + n)*33 + m] = part[n] * inv[n] * SCALE;
        }
    }
    __syncthreads();
    for (int i = t; i < 64*MM; i += 256) {
        int m = i >> 6, nn = i & 63;
        g_Z[(size_t)(b*MM + m)*HWN + n0 + nn] = St[nn*33 + m];
    }
}

// ------------------------------------------------------------------
__global__ __launch_bounds__(256) void k2a() {
    int bm = blockIdx.x;
    int b  = bm >> 5;
    const float* z  = g_Z + (size_t)bm * HWN;
    const float* vv = g_v + b * HWN;
    int t = threadIdx.x;

    float vals[16];
    float mx = -1e30f;
    #pragma unroll
    for (int i = 0; i < 16; ++i) {
        int idx = t + i*256;
        vals[i] = z[idx] + vv[idx];
        mx = fmaxf(mx, vals[i]);
    }
    __shared__ float red[8];
    #pragma unroll
    for (int o = 16; o; o >>= 1) mx = fmaxf(mx, __shfl_xor_sync(~0u, mx, o));
    if ((t & 31) == 0) red[t >> 5] = mx;
    __syncthreads();
    if (t < 8) {
        float r = red[t];
        #pragma unroll
        for (int o = 4; o; o >>= 1) r = fmaxf(r, __shfl_xor_sync(0xff, r, o, 8));
        if (t == 0) red[0] = r;
    }
    __syncthreads();
    mx = red[0];
    __syncthreads();

    float s = 0.f;
    #pragma unroll
    for (int i = 0; i < 16; ++i) s += expf(vals[i] - mx);
    #pragma unroll
    for (int o = 16; o; o >>= 1) s += __shfl_xor_sync(~0u, s, o);
    if ((t & 31) == 0) red[t >> 5] = s;
    __syncthreads();
    if (t == 0) {
        float tot = 0.f;
        #pragma unroll
        for (int i = 0; i < 8; ++i) tot += red[i];
        g_u[bm] = NORMC - (mx + logf(tot));
    }
}

__global__ __launch_bounds__(256) void k2b() {
    int gid = blockIdx.x*256 + threadIdx.x;
    int b = gid >> 12;
    int n = gid & (HWN - 1);
    __shared__ float us[MM];
    if (threadIdx.x < MM) us[threadIdx.x] = g_u[b*MM + threadIdx.x];
    __syncthreads();
    float vals[MM];
    float mx = -1e30f;
    #pragma unroll
    for (int m = 0; m < MM; ++m) {
        vals[m] = g_Z[(size_t)(b*MM + m)*HWN + n] + us[m];
        mx = fmaxf(mx, vals[m]);
    }
    float s = 0.f;
    #pragma unroll
    for (int m = 0; m < MM; ++m) s += expf(vals[m] - mx);
    g_v[gid] = NORMC - (mx + logf(s));
}

// ------------------------------------------------------------------
__global__ __launch_bounds__(256) void k3(const float* __restrict__ xp,
                                          float* __restrict__ vt) {
    int b  = blockIdx.y;
    int n0 = blockIdx.x * 256;
    int t  = threadIdx.x;
    __shared__ float sw[64*36];
    __shared__ float us[MM];
    if (t < MM) us[t] = g_u[b*MM + t];
    float acc[MM];
    #pragma unroll
    for (int m = 0; m < MM; ++m) acc[m] = 0.f;
    __syncthreads();

    for (int sub = 0; sub < 4; ++sub) {
        int ns = n0 + sub*64;
        __syncthreads();
        #pragma unroll
        for (int p = 0; p < 8; ++p) {
            int idx = t + p*256;
            int m = idx >> 6, nn = idx & 63;
            float zv = g_Z[(size_t)(b*MM + m)*HWN + ns + nn];
            sw[nn*36 + m] = expf(zv + us[m] + g_v[b*HWN + ns + nn] - NORMC);
        }
        __syncthreads();
        #pragma unroll 4
        for (int nn = 0; nn < 64; ++nn) {
            float xv = xp[(size_t)(b*HWN + ns + nn)*DD + t]
                     * g_inv[b*HWN + ns + nn];
            #pragma unroll
            for (int m4 = 0; m4 < 8; ++m4) {
                float4 w4 = *(float4*)(sw + nn*36 + m4*4);
                acc[m4*4+0] += xv * w4.x;
                acc[m4*4+1] += xv * w4.y;
                acc[m4*4+2] += xv * w4.z;
                acc[m4*4+3] += xv * w4.w;
            }
        }
    }
    #pragma unroll
    for (int m = 0; m < MM; ++m)
        atomicAdd(&vt[(size_t)(b*MM + m)*DD + t], acc[m]);
}

// ------------------------------------------------------------------
extern "C" void kernel_launch(void* const* d_in, const int* in_sizes, int n_in,
                              void* d_out, int out_size) {
    (void)in_sizes; (void)n_in; (void)out_size;
    const float* x    = (const float*)d_in[0];   // [16,768,64,64]
    const float* W    = (const float*)d_in[1];   // [256,768]
    const float* bias = (const float*)d_in[2];   // [256]
    const float* v    = (const float*)d_in[3];   // [32,256]

    float* out = (float*)d_out;
    float* vt  = out;                 // v_tilde [16,32,256]
    float* xp  = out + VT_ELEMS;      // x_proj  [16,4096,256]

    cudaFuncSetAttribute(k1_mma, cudaFuncAttributeMaxDynamicSharedMemorySize, SMEM_SZ);

    k_init<<<512, 256>>>(vt);
    k_wnorm<<<32, 256>>>(v);
    k_wsplit<<<384, 256>>>(W);
    k1_mma<<<dim3(32, 16), 512, SMEM_SZ>>>(x, bias, xp);
    k1b<<<dim3(64, 16), 256>>>(xp);
    for (int it = 0; it < 3; ++it) {
        k2a<<<512, 256>>>();
        k2b<<<256, 256>>>();
    }
    k3<<<dim3(16, 16), 256>>>(xp, vt);
}

// round 6
// speedup vs baseline: 1.8745x; 1.0105x over previous
#include <cuda_runtime.h>
#include <cuda_bf16.h>
#include <cstdint>
#include <math.h>

#define BB 16
#define CC 768
#define HWN 4096
#define DD 256
#define MM 32
#define SCALE 20.0f            // 1/EPS
#define NORMC (-8.32554830f)   // -log(32+4096)
#define VT_ELEMS (BB*MM*DD)

// ---- scratch (device globals; no allocations allowed) ----
__device__ float g_Z[BB*MM*HWN];     // 8 MB: Z[b,m,n]
__device__ float g_inv[BB*HWN];
__device__ float g_u[BB*MM];
__device__ float g_v[BB*HWN];
__device__ float g_wn[MM*DD];
// W pre-split into per-lane mma A-fragments: [term 2][dtile 16][ktile 48][lane 32][4 words]
__device__ __align__(16) unsigned g_wf[2*98304];

__device__ __forceinline__ uint32_t smem_u32(const void* p) {
    uint32_t a;
    asm("{ .reg .u64 t; cvta.to.shared.u64 t, %1; cvt.u32.u64 %0, t; }" : "=r"(a) : "l"(p));
    return a;
}

__device__ __forceinline__ void split2(float a, float b, unsigned &hi, unsigned &lo) {
    __nv_bfloat16 ha = __float2bfloat16_rn(a), hb = __float2bfloat16_rn(b);
    float ra = a - __bfloat162float(ha), rb = b - __bfloat162float(hb);
    __nv_bfloat16 la = __float2bfloat16_rn(ra), lb = __float2bfloat16_rn(rb);
    hi = (unsigned)__bfloat16_as_ushort(ha) | ((unsigned)__bfloat16_as_ushort(hb) << 16);
    lo = (unsigned)__bfloat16_as_ushort(la) | ((unsigned)__bfloat16_as_ushort(lb) << 16);
}

#define LDSM_T(r0,r1,r2,r3,addr) \
    asm volatile("ldmatrix.sync.aligned.m8n8.x4.trans.shared.b16 {%0,%1,%2,%3}, [%4];" \
        : "=r"(r0), "=r"(r1), "=r"(r2), "=r"(r3) : "r"(addr))

#define MMA_BF16(acc, a, b0v, b1v) \
    asm volatile("mma.sync.aligned.m16n8k16.row.col.f32.bf16.bf16.f32 " \
        "{%0,%1,%2,%3}, {%4,%5,%6,%7}, {%8,%9}, {%0,%1,%2,%3};" \
        : "+f"((acc)[0]), "+f"((acc)[1]), "+f"((acc)[2]), "+f"((acc)[3]) \
        : "r"((a).x), "r"((a).y), "r"((a).z), "r"((a).w), "r"(b0v), "r"(b1v))

// ------------------------------------------------------------------
__global__ __launch_bounds__(256) void k_init(float* __restrict__ vt) {
    int i = blockIdx.x * 256 + threadIdx.x;
    if (i < BB*HWN) g_v[i] = 0.0f;
    if (i < VT_ELEMS) vt[i] = 0.0f;
}

// ------------------------------------------------------------------
__global__ __launch_bounds__(256) void k_wnorm(const float* __restrict__ v) {
    int r = blockIdx.x, t = threadIdx.x;
    float val = v[r*DD + t];
    float s = val * val;
    #pragma unroll
    for (int o = 16; o; o >>= 1) s += __shfl_xor_sync(~0u, s, o);
    __shared__ float red[8];
    if ((t & 31) == 0) red[t >> 5] = s;
    __syncthreads();
    if (t < 8) {
        float r2 = red[t];
        #pragma unroll
        for (int o = 4; o; o >>= 1) r2 += __shfl_xor_sync(0xff, r2, o, 8);
        if (t == 0) red[0] = r2;
    }
    __syncthreads();
    float inv = 1.0f / fmaxf(sqrtf(red[0]), 1e-12f);
    g_wn[r*DD + t] = val * inv;
}

// ------------------------------------------------------------------
// Pre-split W (fp32 -> bf16 hi/lo) into per-lane A-fragment layout.
//   d = dt*16 + (lane>>2) + (w&1)*8 ; c = kt*16 + (lane&3)*2 + (w>>1)*8
__global__ __launch_bounds__(256) void k_wsplit(const float* __restrict__ W) {
    int gid = blockIdx.x*256 + threadIdx.x;      // 0..98303
    int w = gid & 3, lane = (gid >> 2) & 31, tile = gid >> 7;
    int kt = tile % 48, dt = tile / 48;
    int d = dt*16 + (lane >> 2) + (w & 1)*8;
    int c = kt*16 + (lane & 3)*2 + (w >> 1)*8;
    unsigned hi, lo;
    split2(W[(size_t)d*CC + c], W[(size_t)d*CC + c + 1], hi, lo);
    g_wf[gid] = hi;
    g_wf[98304 + gid] = lo;
}

// ------------------------------------------------------------------
// k1_mma: x_proj[b,n,d] = W x + bias via mma.sync bf16 3-term split.
// CTA: 128 d x 128 n, 256 threads (8 warps), 2 CTAs/SM for overlap.
// Warp: 32 d x 64 n. Double-buffered x staging, 16-k chunks.
#define XPITCH 304                      // smem row pitch (bytes)
#define XLO    4864                     // hi->lo offset within buffer (16*304)
#define XBUF   9728                     // one x buffer (hi + lo)
#define EP_OFF 19456                    // epilogue staging region
#define EPITCH 132                      // epilogue float pitch (128 d + pad)
#define SMEM_SZ (EP_OFF + 64*EPITCH*4) // 19456 + 33792 = 53248

__global__ __launch_bounds__(256, 2) void k1_mma(const float* __restrict__ x,
                                                 const float* __restrict__ bias,
                                                 float* __restrict__ xp) {
    extern __shared__ char smc[];
    const uint32_t sb = smem_u32(smc);
    const int b = blockIdx.y >> 1, dh = blockIdx.y & 1;
    const int n0 = blockIdx.x * 128;
    const int t = threadIdx.x, w = t >> 5, lane = t & 31;
    const int nw = (w >> 2) * 64;

    float acc[2][8][4];
    #pragma unroll
    for (int mt = 0; mt < 2; ++mt)
        #pragma unroll
        for (int nt = 0; nt < 8; ++nt)
            #pragma unroll
            for (int i = 0; i < 4; ++i) acc[mt][nt][i] = 0.f;

    const float* xb = x + (size_t)b * CC * HWN + n0;
    const int c0 = t >> 5;              // staging row 0..7
    const int c1 = c0 + 8;              // staging row 8..15
    const int n4 = t & 31;              // float4 column

    // prefetch chunk 0 (16 k-rows)
    float4 v0 = *(const float4*)(xb + (size_t)c0*HWN + n4*4);
    float4 v1 = *(const float4*)(xb + (size_t)c1*HWN + n4*4);

    int buf = 0;
    for (int kc = 0; kc < CC; kc += 16, buf ^= 1) {
        // STS prefetched chunk into buf
        {
            char* base = smc + buf*XBUF;
            unsigned h01,l01,h23,l23;
            split2(v0.x, v0.y, h01, l01);
            split2(v0.z, v0.w, h23, l23);
            char* r0 = base + c0*XPITCH + n4*8;
            *(uint2*)r0         = make_uint2(h01, h23);
            *(uint2*)(r0 + XLO) = make_uint2(l01, l23);
            split2(v1.x, v1.y, h01, l01);
            split2(v1.z, v1.w, h23, l23);
            char* r1 = base + c1*XPITCH + n4*8;
            *(uint2*)r1         = make_uint2(h01, h23);
            *(uint2*)(r1 + XLO) = make_uint2(l01, l23);
        }
        // prefetch next chunk (overlaps MMA below)
        if (kc + 16 < CC) {
            v0 = *(const float4*)(xb + (size_t)(kc + 16 + c0)*HWN + n4*4);
            v1 = *(const float4*)(xb + (size_t)(kc + 16 + c1)*HWN + n4*4);
        }
        __syncthreads();

        const uint32_t sxb = sb + buf*XBUF;
        const int kt = kc >> 4;
        uint4 ah[2], al[2];
        #pragma unroll
        for (int mt = 0; mt < 2; ++mt) {
            int dt = dh*8 + (w & 3)*2 + mt;
            int off = ((dt*48 + kt)*32 + lane)*4;
            ah[mt] = *(const uint4*)(g_wf + off);
            al[mt] = *(const uint4*)(g_wf + 98304 + off);
        }
        #pragma unroll
        for (int j = 0; j < 4; ++j) {
            uint32_t baddr = sxb + (uint32_t)((lane & 15)*XPITCH
                           + (nw + j*16 + ((lane >> 4) << 3))*2);
            unsigned bh0,bh1,bh2,bh3, bl0,bl1,bl2,bl3;
            LDSM_T(bh0,bh1,bh2,bh3, baddr);
            LDSM_T(bl0,bl1,bl2,bl3, baddr + XLO);
            #pragma unroll
            for (int mt = 0; mt < 2; ++mt) {
                MMA_BF16(acc[mt][2*j],   ah[mt], bh0, bh1);
                MMA_BF16(acc[mt][2*j],   ah[mt], bl0, bl1);
                MMA_BF16(acc[mt][2*j],   al[mt], bh0, bh1);
                MMA_BF16(acc[mt][2*j+1], ah[mt], bh2, bh3);
                MMA_BF16(acc[mt][2*j+1], ah[mt], bl2, bl3);
                MMA_BF16(acc[mt][2*j+1], al[mt], bh2, bh3);
            }
        }
        // next STS targets other buffer; safe without trailing sync
    }

    // epilogue: stage per 64-n half for coalesced stores of 128 d
    float* s_ep = (float*)(smc + EP_OFF);
    const float4* bias4 = (const float4*)bias;
    #pragma unroll
    for (int p = 0; p < 2; ++p) {
        __syncthreads();
        if ((w >> 2) == p) {
            #pragma unroll
            for (int mt = 0; mt < 2; ++mt) {
                int d = (w & 3)*32 + mt*16 + (lane >> 2);
                #pragma unroll
                for (int nt = 0; nt < 8; ++nt) {
                    int nl = nt*8 + (lane & 3)*2;
                    s_ep[nl*EPITCH + d]           = acc[mt][nt][0];
                    s_ep[(nl+1)*EPITCH + d]       = acc[mt][nt][1];
                    s_ep[nl*EPITCH + d + 8]       = acc[mt][nt][2];
                    s_ep[(nl+1)*EPITCH + d + 8]   = acc[mt][nt][3];
                }
            }
        }
        __syncthreads();
        #pragma unroll
        for (int i = 0; i < 8; ++i) {
            int idx = t + i*256;              // 2048 float4 items
            int row = idx >> 5, c4 = idx & 31;
            float4 v = *(float4*)(s_ep + row*EPITCH + c4*4);
            float4 bv = bias4[dh*32 + c4];
            v.x += bv.x; v.y += bv.y; v.z += bv.z; v.w += bv.w;
            *(float4*)(xp + (size_t)(b*HWN + n0 + p*64 + row)*DD + dh*128 + c4*4) = v;
        }
    }
}

// ------------------------------------------------------------------
// k1b: row L2 norms + cluster scores -> Z (reads x_proj)
__global__ __launch_bounds__(256) void k1b(const float* __restrict__ xp) {
    const int b = blockIdx.y, n0 = blockIdx.x * 64;
    const int t = threadIdx.x, tx = t & 15, ty = t >> 4;
    __shared__ float sh[8192 + 64*33];

    float4 acc[4][4];
    #pragma unroll
    for (int n = 0; n < 4; ++n) {
        int row = b*HWN + n0 + ty*4 + n;
        #pragma unroll
        for (int j = 0; j < 4; ++j)
            acc[n][j] = *(const float4*)(xp + (size_t)row*DD + tx*4 + 64*j);
    }

    float inv[4];
    #pragma unroll
    for (int n = 0; n < 4; ++n) {
        int row = b*HWN + n0 + ty*4 + n;
        float s = 0.f;
        #pragma unroll
        for (int j = 0; j < 4; ++j)
            s += acc[n][j].x*acc[n][j].x + acc[n][j].y*acc[n][j].y
               + acc[n][j].z*acc[n][j].z + acc[n][j].w*acc[n][j].w;
        #pragma unroll
        for (int o = 8; o; o >>= 1) s += __shfl_xor_sync(~0u, s, o, 16);
        inv[n] = 1.0f / fmaxf(sqrtf(s), 1e-12f);
        if (tx == 0) g_inv[row] = inv[n];
    }

    float* Wn = sh;
    float* St = sh + 8192;
    for (int i = t; i < MM*DD; i += 256) Wn[i] = g_wn[i];
    __syncthreads();

    for (int m = 0; m < MM; ++m) {
        float part[4] = {0.f, 0.f, 0.f, 0.f};
        #pragma unroll
        for (int j = 0; j < 4; ++j) {
            float4 wv = *(float4*)(Wn + m*DD + tx*4 + 64*j);
            #pragma unroll
            for (int n = 0; n < 4; ++n)
                part[n] += acc[n][j].x*wv.x + acc[n][j].y*wv.y
                         + acc[n][j].z*wv.z + acc[n][j].w*wv.w;
        }
        #pragma unroll
        for (int n = 0; n < 4; ++n) {
            #pragma unroll
            for (int o = 8; o; o >>= 1)
                part[n] += __shfl_xor_sync(~0u, part[n], o, 16);
            if (tx == 0) St[(ty*4 + n)*33 + m] = part[n] * inv[n] * SCALE;
        }
    }
    __syncthreads();
    for (int i = t; i < 64*MM; i += 256) {
        int m = i >> 6, nn = i & 63;
        g_Z[(size_t)(b*MM + m)*HWN + n0 + nn] = St[nn*33 + m];
    }
}

// ------------------------------------------------------------------
__global__ __launch_bounds__(256) void k2a() {
    int bm = blockIdx.x;
    int b  = bm >> 5;
    const float* z  = g_Z + (size_t)bm * HWN;
    const float* vv = g_v + b * HWN;
    int t = threadIdx.x;

    float vals[16];
    float mx = -1e30f;
    #pragma unroll
    for (int i = 0; i < 16; ++i) {
        int idx = t + i*256;
        vals[i] = z[idx] + vv[idx];
        mx = fmaxf(mx, vals[i]);
    }
    __shared__ float red[8];
    #pragma unroll
    for (int o = 16; o; o >>= 1) mx = fmaxf(mx, __shfl_xor_sync(~0u, mx, o));
    if ((t & 31) == 0) red[t >> 5] = mx;
    __syncthreads();
    if (t < 8) {
        float r = red[t];
        #pragma unroll
        for (int o = 4; o; o >>= 1) r = fmaxf(r, __shfl_xor_sync(0xff, r, o, 8));
        if (t == 0) red[0] = r;
    }
    __syncthreads();
    mx = red[0];
    __syncthreads();

    float s = 0.f;
    #pragma unroll
    for (int i = 0; i < 16; ++i) s += expf(vals[i] - mx);
    #pragma unroll
    for (int o = 16; o; o >>= 1) s += __shfl_xor_sync(~0u, s, o);
    if ((t & 31) == 0) red[t >> 5] = s;
    __syncthreads();
    if (t == 0) {
        float tot = 0.f;
        #pragma unroll
        for (int i = 0; i < 8; ++i) tot += red[i];
        g_u[bm] = NORMC - (mx + logf(tot));
    }
}

__global__ __launch_bounds__(256) void k2b() {
    int gid = blockIdx.x*256 + threadIdx.x;
    int b = gid >> 12;
    int n = gid & (HWN - 1);
    __shared__ float us[MM];
    if (threadIdx.x < MM) us[threadIdx.x] = g_u[b*MM + threadIdx.x];
    __syncthreads();
    float vals[MM];
    float mx = -1e30f;
    #pragma unroll
    for (int m = 0; m < MM; ++m) {
        vals[m] = g_Z[(size_t)(b*MM + m)*HWN + n] + us[m];
        mx = fmaxf(mx, vals[m]);
    }
    float s = 0.f;
    #pragma unroll
    for (int m = 0; m < MM; ++m) s += expf(vals[m] - mx);
    g_v[gid] = NORMC - (mx + logf(s));
}

// ------------------------------------------------------------------
__global__ __launch_bounds__(256) void k3(const float* __restrict__ xp,
                                          float* __restrict__ vt) {
    int b  = blockIdx.y;
    int n0 = blockIdx.x * 256;
    int t  = threadIdx.x;
    __shared__ float sw[64*36];
    __shared__ float us[MM];
    if (t < MM) us[t] = g_u[b*MM + t];
    float acc[MM];
    #pragma unroll
    for (int m = 0; m < MM; ++m) acc[m] = 0.f;
    __syncthreads();

    for (int sub = 0; sub < 4; ++sub) {
        int ns = n0 + sub*64;
        __syncthreads();
        #pragma unroll
        for (int p = 0; p < 8; ++p) {
            int idx = t + p*256;
            int m = idx >> 6, nn = idx & 63;
            float zv = g_Z[(size_t)(b*MM + m)*HWN + ns + nn];
            sw[nn*36 + m] = expf(zv + us[m] + g_v[b*HWN + ns + nn] - NORMC);
        }
        __syncthreads();
        #pragma unroll 4
        for (int nn = 0; nn < 64; ++nn) {
            float xv = xp[(size_t)(b*HWN + ns + nn)*DD + t]
                     * g_inv[b*HWN + ns + nn];
            #pragma unroll
            for (int m4 = 0; m4 < 8; ++m4) {
                float4 w4 = *(float4*)(sw + nn*36 + m4*4);
                acc[m4*4+0] += xv * w4.x;
                acc[m4*4+1] += xv * w4.y;
                acc[m4*4+2] += xv * w4.z;
                acc[m4*4+3] += xv * w4.w;
            }
        }
    }
    #pragma unroll
    for (int m = 0; m < MM; ++m)
        atomicAdd(&vt[(size_t)(b*MM + m)*DD + t], acc[m]);
}

// ------------------------------------------------------------------
extern "C" void kernel_launch(void* const* d_in, const int* in_sizes, int n_in,
                              void* d_out, int out_size) {
    (void)in_sizes; (void)n_in; (void)out_size;
    const float* x    = (const float*)d_in[0];   // [16,768,64,64]
    const float* W    = (const float*)d_in[1];   // [256,768]
    const float* bias = (const float*)d_in[2];   // [256]
    const float* v    = (const float*)d_in[3];   // [32,256]

    float* out = (float*)d_out;
    float* vt  = out;                 // v_tilde [16,32,256]
    float* xp  = out + VT_ELEMS;      // x_proj  [16,4096,256]

    cudaFuncSetAttribute(k1_mma, cudaFuncAttributeMaxDynamicSharedMemorySize, SMEM_SZ);

    k_init<<<512, 256>>>(vt);
    k_wnorm<<<32, 256>>>(v);
    k_wsplit<<<384, 256>>>(W);
    k1_mma<<<dim3(32, 32), 256, SMEM_SZ>>>(x, bias, xp);
    k1b<<<dim3(64, 16), 256>>>(xp);
    for (int it = 0; it < 3; ++it) {
        k2a<<<512, 256>>>();
        k2b<<<256, 256>>>();
    }
    k3<<<dim3(16, 16), 256>>>(xp, vt);
}